// round 1
// baseline (speedup 1.0000x reference)
#include <cuda_runtime.h>

#define NB 8192      // batch
#define ND 512       // dim
#define NK 16384     // clusters
#define NSLICE 8
#define SLICE_COLS (NK / NSLICE)   // 2048
#define BM 128
#define BN 128
#define BK 16
#define INV_TEMP 2.0f
#define EPS_N 1e-12f

// ---- scratch (static device allocations are allowed) ----
static __device__ float g_embN[NB * ND];        // normalized emb, pre-scaled by 1/T
static __device__ float g_protoN[NK * ND];      // normalized prototypes
static __device__ float g_mpart[NB * NSLICE];
static __device__ float g_spart[NB * NSLICE];
static __device__ float g_pos[NB];
static __device__ int   g_cid[NB];
static __device__ int   g_counts[NK];
static __device__ int   g_ranks[NB];
static __device__ int   g_is64;

__device__ __forceinline__ float pow09(int n) {
    float r = 1.0f;
    for (int i = 0; i < n; i++) r *= 0.9f;
    return r;
}

// ---- dtype detection: int64 ids have all-zero high words ----
__global__ void detect_kernel(const int* __restrict__ raw) {
    __shared__ int s;
    if (threadIdx.x == 0) s = 0;
    __syncthreads();
    int acc = 0;
    for (int i = threadIdx.x; i < NB / 2; i += blockDim.x)
        acc |= raw[2 * i + 1];
    atomicOr(&s, acc);
    __syncthreads();
    if (threadIdx.x == 0) g_is64 = (s == 0) ? 1 : 0;
}

__global__ void convert_cid_kernel(const int* __restrict__ raw) {
    int b = blockIdx.x * blockDim.x + threadIdx.x;
    if (b < NB) g_cid[b] = g_is64 ? raw[2 * b] : raw[b];
}

// ---- L2 normalize: one warp per row ----
__global__ void l2norm_kernel(const float* __restrict__ src, int rows,
                              float extra, int dst_sel) {
    int warp = (blockIdx.x * blockDim.x + threadIdx.x) >> 5;
    int lane = threadIdx.x & 31;
    if (warp >= rows) return;
    const float4* p = (const float4*)(src + (size_t)warp * ND);
    float4 v[4];
    float s = 0.f;
#pragma unroll
    for (int q = 0; q < 4; q++) {
        v[q] = p[lane + 32 * q];
        s += v[q].x * v[q].x + v[q].y * v[q].y + v[q].z * v[q].z + v[q].w * v[q].w;
    }
#pragma unroll
    for (int o = 16; o; o >>= 1) s += __shfl_xor_sync(0xffffffffu, s, o);
    float sc = extra / fmaxf(sqrtf(s), EPS_N);
    float* dst = dst_sel ? g_protoN : g_embN;
    float4* d = (float4*)(dst + (size_t)warp * ND);
#pragma unroll
    for (int q = 0; q < 4; q++)
        d[lane + 32 * q] = make_float4(v[q].x * sc, v[q].y * sc, v[q].z * sc, v[q].w * sc);
}

__global__ void zero_counts_kernel() {
    int i = blockIdx.x * blockDim.x + threadIdx.x;
    if (i < NK) g_counts[i] = 0;
}

__global__ void count_kernel() {
    int b = blockIdx.x * blockDim.x + threadIdx.x;
    if (b < NB) atomicAdd(&g_counts[g_cid[b]], 1);
}

// rank of b = #{j < b : cid[j] == cid[b]}
__global__ void rank_kernel() {
    __shared__ int sc[2048];
    int b = blockIdx.x * blockDim.x + threadIdx.x;
    int myc = g_cid[b];
    int r = 0;
    for (int base = 0; base < NB; base += 2048) {
        for (int j = threadIdx.x; j < 2048; j += blockDim.x)
            sc[j] = g_cid[base + j];
        __syncthreads();
        int lim = b - base;
        if (lim > 2048) lim = 2048;
        for (int j = 0; j < lim; j++) r += (sc[j] == myc);
        __syncthreads();
    }
    g_ranks[b] = r;
}

// ---- fused GEMM (128x128 tiles, fp32) + online masked LSE ----
__global__ __launch_bounds__(256, 2) void gemm_lse_kernel() {
    __shared__ float As[BK][BM];
    __shared__ float Bs[BK][BN];
    const int tid = threadIdx.x;
    const int tx = tid & 15, ty = tid >> 4;
    const int mbase = blockIdx.x * BM;
    const int nstart = blockIdx.y * SLICE_COLS;

    int myc[8];
#pragma unroll
    for (int i = 0; i < 8; i++) myc[i] = g_cid[mbase + ty * 8 + i];

    float m_run[8], s_run[8];
#pragma unroll
    for (int i = 0; i < 8; i++) { m_run[i] = -1e30f; s_run[i] = 0.f; }

    const int f4base = tid * 2;   // 512 float4 per tile, 2 per thread

    for (int nt = 0; nt < SLICE_COLS / BN; nt++) {
        const int nbase = nstart + nt * BN;
        float acc[8][8];
#pragma unroll
        for (int i = 0; i < 8; i++)
#pragma unroll
            for (int j = 0; j < 8; j++) acc[i][j] = 0.f;

        for (int d0 = 0; d0 < ND; d0 += BK) {
#pragma unroll
            for (int q = 0; q < 2; q++) {
                int f4  = f4base + q;
                int row = f4 >> 2;
                int d4  = f4 & 3;
                float4 va = *(const float4*)&g_embN[(size_t)(mbase + row) * ND + d0 + d4 * 4];
                As[d4 * 4 + 0][row] = va.x;
                As[d4 * 4 + 1][row] = va.y;
                As[d4 * 4 + 2][row] = va.z;
                As[d4 * 4 + 3][row] = va.w;
                float4 vb = *(const float4*)&g_protoN[(size_t)(nbase + row) * ND + d0 + d4 * 4];
                Bs[d4 * 4 + 0][row] = vb.x;
                Bs[d4 * 4 + 1][row] = vb.y;
                Bs[d4 * 4 + 2][row] = vb.z;
                Bs[d4 * 4 + 3][row] = vb.w;
            }
            __syncthreads();
#pragma unroll
            for (int kk = 0; kk < BK; kk++) {
                const float4* Ap = (const float4*)&As[kk][ty * 8];
                const float4* Bp = (const float4*)&Bs[kk][tx * 8];
                float4 a0 = Ap[0], a1 = Ap[1];
                float4 b0 = Bp[0], b1 = Bp[1];
                float a[8] = {a0.x, a0.y, a0.z, a0.w, a1.x, a1.y, a1.z, a1.w};
                float b[8] = {b0.x, b0.y, b0.z, b0.w, b1.x, b1.y, b1.z, b1.w};
#pragma unroll
                for (int i = 0; i < 8; i++)
#pragma unroll
                    for (int j = 0; j < 8; j++)
                        acc[i][j] = fmaf(a[i], b[j], acc[i][j]);
            }
            __syncthreads();
        }

        // epilogue: online max/sum per row across the 16 tx lanes
#pragma unroll
        for (int i = 0; i < 8; i++) {
            float tmax = acc[i][0];
#pragma unroll
            for (int j = 1; j < 8; j++) tmax = fmaxf(tmax, acc[i][j]);
#pragma unroll
            for (int o = 8; o; o >>= 1)
                tmax = fmaxf(tmax, __shfl_xor_sync(0xffffffffu, tmax, o));
            float newm = fmaxf(m_run[i], tmax);
            int jp = myc[i] - nbase - tx * 8;   // local col of positive, if in my 8
            float lsum = 0.f;
#pragma unroll
            for (int j = 0; j < 8; j++) {
                float e = __expf(acc[i][j] - newm);
                if (j == jp) { g_pos[mbase + ty * 8 + i] = acc[i][j]; e = 0.f; }
                lsum += e;
            }
#pragma unroll
            for (int o = 8; o; o >>= 1)
                lsum += __shfl_xor_sync(0xffffffffu, lsum, o);
            s_run[i] = s_run[i] * __expf(m_run[i] - newm) + lsum;
            m_run[i] = newm;
        }
    }

    if (tx == 0) {
#pragma unroll
        for (int i = 0; i < 8; i++) {
            int row = mbase + ty * 8 + i;
            g_mpart[row * NSLICE + blockIdx.y] = m_run[i];
            g_spart[row * NSLICE + blockIdx.y] = s_run[i];
        }
    }
}

// ---- EMA closed form: out = 0.9^m * proto ----
__global__ void proto_copy_kernel(const float* __restrict__ proto, float* __restrict__ out) {
    int idx = blockIdx.x * blockDim.x + threadIdx.x;
    if (idx < NK * ND) {
        int k = idx >> 9;
        out[1 + idx] = proto[idx] * pow09(g_counts[k]);
    }
}

// ---- out[c] += 0.1 * 0.9^(m-1-r) * x_b ----
__global__ void scatter_kernel(const float* __restrict__ emb, float* __restrict__ out) {
    int b = blockIdx.x;
    int c = g_cid[b];
    int mc = g_counts[c];
    int rb = g_ranks[b];
    float w = 0.1f * pow09(mc - 1 - rb);
    float* dst = out + 1 + (size_t)c * ND;
    const float* x = emb + (size_t)b * ND;
    for (int d = threadIdx.x; d < ND; d += blockDim.x)
        atomicAdd(&dst[d], w * x[d]);
}

// ---- merge slice partials, compute mean loss ----
__global__ void loss_kernel(float* __restrict__ out) {
    __shared__ float red[256];
    int tid = threadIdx.x;
    float acc = 0.f;
    for (int r = tid; r < NB; r += 256) {
        float M = -1e30f;
#pragma unroll
        for (int s = 0; s < NSLICE; s++) M = fmaxf(M, g_mpart[r * NSLICE + s]);
        float S = 0.f;
#pragma unroll
        for (int s = 0; s < NSLICE; s++)
            S += g_spart[r * NSLICE + s] * __expf(g_mpart[r * NSLICE + s] - M);
        acc += (M + logf(S)) - g_pos[r];
    }
    red[tid] = acc;
    __syncthreads();
    for (int o = 128; o; o >>= 1) {
        if (tid < o) red[tid] += red[tid + o];
        __syncthreads();
    }
    if (tid == 0) out[0] = red[0] / (float)NB;
}

extern "C" void kernel_launch(void* const* d_in, const int* in_sizes, int n_in,
                              void* d_out, int out_size) {
    const float* emb   = (const float*)d_in[0];
    const int*   cidr  = (const int*)d_in[1];
    const float* proto = (const float*)d_in[2];
    float* out = (float*)d_out;

    detect_kernel<<<1, 256>>>(cidr);
    convert_cid_kernel<<<NB / 256, 256>>>(cidr);

    l2norm_kernel<<<NB / 8, 256>>>(emb, NB, INV_TEMP, 0);
    l2norm_kernel<<<NK / 8, 256>>>(proto, NK, 1.0f, 1);

    zero_counts_kernel<<<NK / 256, 256>>>();
    count_kernel<<<NB / 256, 256>>>();
    rank_kernel<<<NB / 256, 256>>>();

    gemm_lse_kernel<<<dim3(NB / BM, NSLICE), 256>>>();

    proto_copy_kernel<<<(NK * ND) / 256, 256>>>(proto, out);
    scatter_kernel<<<NB, 128>>>(emb, out);

    loss_kernel<<<1, 256>>>(out);
}

// round 2
// speedup vs baseline: 1.0005x; 1.0005x over previous
#include <cuda_runtime.h>

#define NB 8192      // batch
#define ND 512       // dim
#define NK 16384     // clusters
#define NSLICE 8
#define SLICE_COLS (NK / NSLICE)   // 2048
#define BM 128
#define BN 128
#define BK 16
#define INV_TEMP 2.0f
#define EPS_N 1e-12f

// ---- scratch (static device allocations are allowed) ----
static __device__ float g_embN[NB * ND];        // normalized emb, pre-scaled by 1/T
static __device__ float g_protoN[NK * ND];      // normalized prototypes
static __device__ float g_mpart[NB * NSLICE];
static __device__ float g_spart[NB * NSLICE];
static __device__ float g_pos[NB];
static __device__ int   g_cid[NB];
static __device__ int   g_counts[NK];
static __device__ int   g_ranks[NB];
static __device__ int   g_is64;

__device__ __forceinline__ float pow09(int n) {
    float r = 1.0f;
    for (int i = 0; i < n; i++) r *= 0.9f;
    return r;
}

// ---- dtype detection: int64 ids have all-zero high words ----
__global__ void detect_kernel(const int* __restrict__ raw) {
    __shared__ int s;
    if (threadIdx.x == 0) s = 0;
    __syncthreads();
    int acc = 0;
    for (int i = threadIdx.x; i < NB / 2; i += blockDim.x)
        acc |= raw[2 * i + 1];
    atomicOr(&s, acc);
    __syncthreads();
    if (threadIdx.x == 0) g_is64 = (s == 0) ? 1 : 0;
}

__global__ void convert_cid_kernel(const int* __restrict__ raw) {
    int b = blockIdx.x * blockDim.x + threadIdx.x;
    if (b < NB) g_cid[b] = g_is64 ? raw[2 * b] : raw[b];
}

// ---- L2 normalize: one warp per row ----
__global__ void l2norm_kernel(const float* __restrict__ src, int rows,
                              float extra, int dst_sel) {
    int warp = (blockIdx.x * blockDim.x + threadIdx.x) >> 5;
    int lane = threadIdx.x & 31;
    if (warp >= rows) return;
    const float4* p = (const float4*)(src + (size_t)warp * ND);
    float4 v[4];
    float s = 0.f;
#pragma unroll
    for (int q = 0; q < 4; q++) {
        v[q] = p[lane + 32 * q];
        s += v[q].x * v[q].x + v[q].y * v[q].y + v[q].z * v[q].z + v[q].w * v[q].w;
    }
#pragma unroll
    for (int o = 16; o; o >>= 1) s += __shfl_xor_sync(0xffffffffu, s, o);
    float sc = extra / fmaxf(sqrtf(s), EPS_N);
    float* dst = dst_sel ? g_protoN : g_embN;
    float4* d = (float4*)(dst + (size_t)warp * ND);
#pragma unroll
    for (int q = 0; q < 4; q++)
        d[lane + 32 * q] = make_float4(v[q].x * sc, v[q].y * sc, v[q].z * sc, v[q].w * sc);
}

__global__ void zero_counts_kernel() {
    int i = blockIdx.x * blockDim.x + threadIdx.x;
    if (i < NK) g_counts[i] = 0;
}

__global__ void count_kernel() {
    int b = blockIdx.x * blockDim.x + threadIdx.x;
    if (b < NB) atomicAdd(&g_counts[g_cid[b]], 1);
}

// rank of b = #{j < b : cid[j] == cid[b]}
__global__ void rank_kernel() {
    __shared__ int sc[2048];
    int b = blockIdx.x * blockDim.x + threadIdx.x;
    int myc = g_cid[b];
    int r = 0;
    for (int base = 0; base < NB; base += 2048) {
        for (int j = threadIdx.x; j < 2048; j += blockDim.x)
            sc[j] = g_cid[base + j];
        __syncthreads();
        int lim = b - base;
        if (lim > 2048) lim = 2048;
        for (int j = 0; j < lim; j++) r += (sc[j] == myc);
        __syncthreads();
    }
    g_ranks[b] = r;
}

// ---- fused GEMM (128x128 tiles, fp32) + online masked LSE ----
__global__ __launch_bounds__(256, 2) void gemm_lse_kernel() {
    __shared__ float As[BK][BM];
    __shared__ float Bs[BK][BN];
    const int tid = threadIdx.x;
    const int tx = tid & 15, ty = tid >> 4;
    const int mbase = blockIdx.x * BM;
    const int nstart = blockIdx.y * SLICE_COLS;

    int myc[8];
#pragma unroll
    for (int i = 0; i < 8; i++) myc[i] = g_cid[mbase + ty * 8 + i];

    float m_run[8], s_run[8];
#pragma unroll
    for (int i = 0; i < 8; i++) { m_run[i] = -1e30f; s_run[i] = 0.f; }

    const int f4base = tid * 2;   // 512 float4 per tile, 2 per thread

    for (int nt = 0; nt < SLICE_COLS / BN; nt++) {
        const int nbase = nstart + nt * BN;
        float acc[8][8];
#pragma unroll
        for (int i = 0; i < 8; i++)
#pragma unroll
            for (int j = 0; j < 8; j++) acc[i][j] = 0.f;

        for (int d0 = 0; d0 < ND; d0 += BK) {
#pragma unroll
            for (int q = 0; q < 2; q++) {
                int f4  = f4base + q;
                int row = f4 >> 2;
                int d4  = f4 & 3;
                float4 va = *(const float4*)&g_embN[(size_t)(mbase + row) * ND + d0 + d4 * 4];
                As[d4 * 4 + 0][row] = va.x;
                As[d4 * 4 + 1][row] = va.y;
                As[d4 * 4 + 2][row] = va.z;
                As[d4 * 4 + 3][row] = va.w;
                float4 vb = *(const float4*)&g_protoN[(size_t)(nbase + row) * ND + d0 + d4 * 4];
                Bs[d4 * 4 + 0][row] = vb.x;
                Bs[d4 * 4 + 1][row] = vb.y;
                Bs[d4 * 4 + 2][row] = vb.z;
                Bs[d4 * 4 + 3][row] = vb.w;
            }
            __syncthreads();
#pragma unroll
            for (int kk = 0; kk < BK; kk++) {
                const float4* Ap = (const float4*)&As[kk][ty * 8];
                const float4* Bp = (const float4*)&Bs[kk][tx * 8];
                float4 a0 = Ap[0], a1 = Ap[1];
                float4 b0 = Bp[0], b1 = Bp[1];
                float a[8] = {a0.x, a0.y, a0.z, a0.w, a1.x, a1.y, a1.z, a1.w};
                float b[8] = {b0.x, b0.y, b0.z, b0.w, b1.x, b1.y, b1.z, b1.w};
#pragma unroll
                for (int i = 0; i < 8; i++)
#pragma unroll
                    for (int j = 0; j < 8; j++)
                        acc[i][j] = fmaf(a[i], b[j], acc[i][j]);
            }
            __syncthreads();
        }

        // epilogue: online max/sum per row across the 16 tx lanes
#pragma unroll
        for (int i = 0; i < 8; i++) {
            float tmax = acc[i][0];
#pragma unroll
            for (int j = 1; j < 8; j++) tmax = fmaxf(tmax, acc[i][j]);
#pragma unroll
            for (int o = 8; o; o >>= 1)
                tmax = fmaxf(tmax, __shfl_xor_sync(0xffffffffu, tmax, o));
            float newm = fmaxf(m_run[i], tmax);
            int jp = myc[i] - nbase - tx * 8;   // local col of positive, if in my 8
            float lsum = 0.f;
#pragma unroll
            for (int j = 0; j < 8; j++) {
                float e = __expf(acc[i][j] - newm);
                if (j == jp) { g_pos[mbase + ty * 8 + i] = acc[i][j]; e = 0.f; }
                lsum += e;
            }
#pragma unroll
            for (int o = 8; o; o >>= 1)
                lsum += __shfl_xor_sync(0xffffffffu, lsum, o);
            s_run[i] = s_run[i] * __expf(m_run[i] - newm) + lsum;
            m_run[i] = newm;
        }
    }

    if (tx == 0) {
#pragma unroll
        for (int i = 0; i < 8; i++) {
            int row = mbase + ty * 8 + i;
            g_mpart[row * NSLICE + blockIdx.y] = m_run[i];
            g_spart[row * NSLICE + blockIdx.y] = s_run[i];
        }
    }
}

// ---- EMA closed form: out = 0.9^m * proto ----
__global__ void proto_copy_kernel(const float* __restrict__ proto, float* __restrict__ out) {
    int idx = blockIdx.x * blockDim.x + threadIdx.x;
    if (idx < NK * ND) {
        int k = idx >> 9;
        out[1 + idx] = proto[idx] * pow09(g_counts[k]);
    }
}

// ---- out[c] += 0.1 * 0.9^(m-1-r) * x_b ----
__global__ void scatter_kernel(const float* __restrict__ emb, float* __restrict__ out) {
    int b = blockIdx.x;
    int c = g_cid[b];
    int mc = g_counts[c];
    int rb = g_ranks[b];
    float w = 0.1f * pow09(mc - 1 - rb);
    float* dst = out + 1 + (size_t)c * ND;
    const float* x = emb + (size_t)b * ND;
    for (int d = threadIdx.x; d < ND; d += blockDim.x)
        atomicAdd(&dst[d], w * x[d]);
}

// ---- merge slice partials, compute mean loss ----
__global__ void loss_kernel(float* __restrict__ out) {
    __shared__ float red[256];
    int tid = threadIdx.x;
    float acc = 0.f;
    for (int r = tid; r < NB; r += 256) {
        float M = -1e30f;
#pragma unroll
        for (int s = 0; s < NSLICE; s++) M = fmaxf(M, g_mpart[r * NSLICE + s]);
        float S = 0.f;
#pragma unroll
        for (int s = 0; s < NSLICE; s++)
            S += g_spart[r * NSLICE + s] * __expf(g_mpart[r * NSLICE + s] - M);
        acc += (M + logf(S)) - g_pos[r];
    }
    red[tid] = acc;
    __syncthreads();
    for (int o = 128; o; o >>= 1) {
        if (tid < o) red[tid] += red[tid + o];
        __syncthreads();
    }
    if (tid == 0) out[0] = red[0] / (float)NB;
}

extern "C" void kernel_launch(void* const* d_in, const int* in_sizes, int n_in,
                              void* d_out, int out_size) {
    const float* emb   = (const float*)d_in[0];
    const int*   cidr  = (const int*)d_in[1];
    const float* proto = (const float*)d_in[2];
    float* out = (float*)d_out;

    detect_kernel<<<1, 256>>>(cidr);
    convert_cid_kernel<<<NB / 256, 256>>>(cidr);

    l2norm_kernel<<<NB / 8, 256>>>(emb, NB, INV_TEMP, 0);
    l2norm_kernel<<<NK / 8, 256>>>(proto, NK, 1.0f, 1);

    zero_counts_kernel<<<NK / 256, 256>>>();
    count_kernel<<<NB / 256, 256>>>();
    rank_kernel<<<NB / 256, 256>>>();

    gemm_lse_kernel<<<dim3(NB / BM, NSLICE), 256>>>();

    proto_copy_kernel<<<(NK * ND) / 256, 256>>>(proto, out);
    scatter_kernel<<<NB, 128>>>(emb, out);

    loss_kernel<<<1, 256>>>(out);
}

// round 4
// speedup vs baseline: 7.0303x; 7.0267x over previous
#include <cuda_runtime.h>
#include <cuda_bf16.h>
#include <cstdint>

#define NB 8192
#define ND 512
#define NK 16384
#define EPS_N 1e-12f

// ============ device scratch ============
static __device__ __align__(256) unsigned char g_embImg[NB * ND * 2];    // bf16 tiles, scaled 2/||x||
static __device__ __align__(256) unsigned char g_protoImg[NK * ND * 2];  // bf16 tiles, scaled 1/||p||
static __device__ float g_einv[NB];
static __device__ float g_pinv[NK];
static __device__ float g_ssum[NB];      // per-row masked exp-sum (atomic)
static __device__ float g_pos[NB];
static __device__ float g_fac[NK];
static __device__ int   g_cid[NB];
static __device__ int   g_counts[NK];
static __device__ int   g_ranks[NB];
static __device__ int   g_is64;

// ============ PTX helpers (sm_80-level only: safe on compute_103) ============
__device__ __forceinline__ uint32_t smem_u32(const void* p) {
    uint32_t a;
    asm("{ .reg .u64 t; cvta.to.shared.u64 t, %1; cvt.u32.u64 %0, t; }" : "=r"(a) : "l"(p));
    return a;
}
__device__ __forceinline__ void cpasync16(uint32_t s, const void* g) {
    asm volatile("cp.async.cg.shared.global [%0], [%1], 16;" :: "r"(s), "l"(g));
}
#define CP_COMMIT() asm volatile("cp.async.commit_group;" ::: "memory")
#define CP_WAIT1()  asm volatile("cp.async.wait_group 1;" ::: "memory")

__device__ __forceinline__ void ldsm4(uint32_t addr, uint32_t& r0, uint32_t& r1,
                                      uint32_t& r2, uint32_t& r3) {
    asm volatile("ldmatrix.sync.aligned.m8n8.x4.shared.b16 {%0,%1,%2,%3}, [%4];"
                 : "=r"(r0), "=r"(r1), "=r"(r2), "=r"(r3) : "r"(addr));
}
__device__ __forceinline__ void mma16816(float* d, const uint32_t* a, const uint32_t* b) {
    asm volatile("mma.sync.aligned.m16n8k16.row.col.f32.bf16.bf16.f32 "
                 "{%0,%1,%2,%3},{%4,%5,%6,%7},{%8,%9},{%0,%1,%2,%3};"
                 : "+f"(d[0]), "+f"(d[1]), "+f"(d[2]), "+f"(d[3])
                 : "r"(a[0]), "r"(a[1]), "r"(a[2]), "r"(a[3]), "r"(b[0]), "r"(b[1]));
}

__device__ __forceinline__ float pow09(int n) {
    float r = 1.0f;
    for (int i = 0; i < n; i++) r *= 0.9f;
    return r;
}
__device__ __forceinline__ uint32_t packbf(float a, float b) {
    __nv_bfloat162 h = __float22bfloat162_rn(make_float2(a, b));
    return *reinterpret_cast<uint32_t*>(&h);
}

// ============ small kernels ============
__global__ void detect_kernel(const int* __restrict__ raw) {
    __shared__ int s;
    if (threadIdx.x == 0) s = 0;
    __syncthreads();
    int acc = 0;
    for (int i = threadIdx.x; i < NB / 2; i += blockDim.x) acc |= raw[2 * i + 1];
    atomicOr(&s, acc);
    __syncthreads();
    if (threadIdx.x == 0) g_is64 = (s == 0) ? 1 : 0;
}
__global__ void convert_cid_kernel(const int* __restrict__ raw) {
    int b = blockIdx.x * blockDim.x + threadIdx.x;
    if (b < NB) g_cid[b] = g_is64 ? raw[2 * b] : raw[b];
}

// normalize + bf16 + SW128 tile image write. sel: 0=emb (extra=2), 1=proto (extra=1)
__global__ void l2norm_img_kernel(const float* __restrict__ src, int rows, float extra, int sel) {
    int row = (blockIdx.x * blockDim.x + threadIdx.x) >> 5;
    int lane = threadIdx.x & 31;
    if (row >= rows) return;
    const float4* p = (const float4*)(src + (size_t)row * ND) + lane * 4;
    float4 v0 = p[0], v1 = p[1], v2 = p[2], v3 = p[3];
    float s = v0.x*v0.x+v0.y*v0.y+v0.z*v0.z+v0.w*v0.w + v1.x*v1.x+v1.y*v1.y+v1.z*v1.z+v1.w*v1.w
            + v2.x*v2.x+v2.y*v2.y+v2.z*v2.z+v2.w*v2.w + v3.x*v3.x+v3.y*v3.y+v3.z*v3.z+v3.w*v3.w;
#pragma unroll
    for (int o = 16; o; o >>= 1) s += __shfl_xor_sync(0xffffffffu, s, o);
    float inv = 1.0f / fmaxf(sqrtf(s), EPS_N);
    if (lane == 0) { if (sel) g_pinv[row] = inv; else g_einv[row] = inv; }
    float sc = extra * inv;
    uint4 q0 = make_uint4(packbf(v0.x*sc, v0.y*sc), packbf(v0.z*sc, v0.w*sc),
                          packbf(v1.x*sc, v1.y*sc), packbf(v1.z*sc, v1.w*sc));
    uint4 q1 = make_uint4(packbf(v2.x*sc, v2.y*sc), packbf(v2.z*sc, v2.w*sc),
                          packbf(v3.x*sc, v3.y*sc), packbf(v3.z*sc, v3.w*sc));
    unsigned char* dst = sel ? g_protoImg : g_embImg;
    int tile = row >> 7, r7 = row & 127;
    size_t base = (size_t)tile * 131072 + (size_t)(lane >> 2) * 16384;
    uint32_t o0 = (uint32_t)(r7 * 128 + (lane & 3) * 32);
    uint32_t xr = (uint32_t)((r7 & 7) << 4);
    *(uint4*)(dst + base + (o0 ^ xr)) = q0;
    *(uint4*)(dst + base + ((o0 + 16) ^ xr)) = q1;
}

__global__ void zero_counts_kernel() {
    int i = blockIdx.x * blockDim.x + threadIdx.x;
    if (i < NK) g_counts[i] = 0;
    if (i < NB) g_ssum[i] = 0.f;
}
__global__ void count_kernel() {
    int b = blockIdx.x * blockDim.x + threadIdx.x;
    if (b < NB) atomicAdd(&g_counts[g_cid[b]], 1);
}
__global__ void fac_kernel() {
    int k = blockIdx.x * blockDim.x + threadIdx.x;
    if (k < NK) g_fac[k] = pow09(g_counts[k]);
}
__global__ void rank_kernel() {
    __shared__ int sc[2048];
    int b = blockIdx.x * blockDim.x + threadIdx.x;
    int myc = g_cid[b];
    int r = 0;
    for (int base = 0; base < NB; base += 2048) {
        for (int j = threadIdx.x; j < 2048; j += blockDim.x) sc[j] = g_cid[base + j];
        __syncthreads();
        int lim = b - base;
        if (lim > 2048) lim = 2048;
        for (int j = 0; j < lim; j++) r += (sc[j] == myc);
        __syncthreads();
    }
    g_ranks[b] = r;
}

// exact fp32 positive logit
__global__ void pos_kernel(const float* __restrict__ emb, const float* __restrict__ proto) {
    int b = (blockIdx.x * blockDim.x + threadIdx.x) >> 5;
    int lane = threadIdx.x & 31;
    if (b >= NB) return;
    int c = g_cid[b];
    const float4* pe = (const float4*)(emb + (size_t)b * ND) + lane * 4;
    const float4* pp = (const float4*)(proto + (size_t)c * ND) + lane * 4;
    float s = 0.f;
#pragma unroll
    for (int q = 0; q < 4; q++) {
        float4 a = pe[q], d = pp[q];
        s += a.x*d.x + a.y*d.y + a.z*d.z + a.w*d.w;
    }
#pragma unroll
    for (int o = 16; o; o >>= 1) s += __shfl_xor_sync(0xffffffffu, s, o);
    if (lane == 0) g_pos[b] = 2.0f * g_einv[b] * g_pinv[c] * s;
}

// ============ HMMA GEMM + fused masked exp-sum ============
// grid (64, 2): blockIdx.x = m-tile (128 rows), blockIdx.y = n-slice (8192 cols)
// smem: A resident 128KB (8 chunks of 16KB) + B ring 3 x 16KB
#define SMEM_A_SZ 131072
#define SMEM_B_SZ (3 * 16384)
#define SMEMSZ (SMEM_A_SZ + SMEM_B_SZ)

__global__ __launch_bounds__(256, 1) void gemm_hmma_kernel() {
    extern __shared__ __align__(256) unsigned char smem[];
    const uint32_t sA = smem_u32(smem);
    const uint32_t sB = sA + SMEM_A_SZ;
    const int tid = threadIdx.x, lane = tid & 31, wid = tid >> 5;
    const int warp_m = wid & 1, warp_n = wid >> 1;        // 2 x 4
    const int mbase = blockIdx.x * 128;
    const int slice = blockIdx.y;

    // ---- issue A copy (group 0) ----
    const unsigned char* asrc = g_embImg + (size_t)blockIdx.x * SMEM_A_SZ;
#pragma unroll
    for (int k = 0; k < 32; k++)
        cpasync16(sA + tid * 16 + k * 4096, asrc + tid * 16 + k * 4096);
    CP_COMMIT();

    const unsigned char* bsrc = g_protoImg + (size_t)slice * 8388608;
    // prefetch B chunks 0,1
#pragma unroll
    for (int g = 0; g < 2; g++) {
#pragma unroll
        for (int k = 0; k < 4; k++)
            cpasync16(sB + g * 16384 + tid * 16 + k * 4096,
                      bsrc + (size_t)g * 16384 + tid * 16 + k * 4096);
        CP_COMMIT();
    }

    // ---- per-thread ldmatrix address components ----
    const int ra = lane & 15;                       // A row within 16
    const uint32_t aXor = (uint32_t)((ra & 7) << 4);
    const uint32_t aColSel = (uint32_t)((lane >> 4) << 4);   // 0 or 16
    uint32_t aoff[4];
#pragma unroll
    for (int mi = 0; mi < 4; mi++)
        aoff[mi] = (uint32_t)((warp_m * 64 + mi * 16 + ra) * 128);
    uint32_t acol[4];
#pragma unroll
    for (int ks = 0; ks < 4; ks++)
        acol[ks] = (uint32_t)((ks * 32 + aColSel) ^ aXor);

    const int rb = (lane & 7) + ((lane & 16) ? 8 : 0);
    const uint32_t bXor = (uint32_t)((lane & 7) << 4);
    const uint32_t bColSel = (uint32_t)((lane & 8) ? 16 : 0);
    uint32_t boff[2];
#pragma unroll
    for (int nip = 0; nip < 2; nip++)
        boff[nip] = (uint32_t)((warp_n * 32 + nip * 16 + rb) * 128);
    uint32_t bcol[4];
#pragma unroll
    for (int ks = 0; ks < 4; ks++)
        bcol[ks] = (uint32_t)((ks * 32 + bColSel) ^ bXor);

    // positive-column ids for my 8 rows
    int mylo[4], myhi[4];
#pragma unroll
    for (int mi = 0; mi < 4; mi++) {
        int r = mbase + warp_m * 64 + mi * 16 + (lane >> 2);
        mylo[mi] = g_cid[r];
        myhi[mi] = g_cid[r + 8];
    }

    float racc[8];
#pragma unroll
    for (int j = 0; j < 8; j++) racc[j] = 0.f;

    int g = 0;
#pragma unroll 1
    for (int nt = 0; nt < 64; nt++) {
        float acc[4][4][4];
#pragma unroll
        for (int mi = 0; mi < 4; mi++)
#pragma unroll
            for (int ni = 0; ni < 4; ni++)
#pragma unroll
                for (int e = 0; e < 4; e++) acc[mi][ni][e] = 0.f;

#pragma unroll 1
        for (int c = 0; c < 8; c++, g++) {
            CP_WAIT1();
            __syncthreads();
            int gn = g + 2;
            if (gn < 512) {
#pragma unroll
                for (int k = 0; k < 4; k++)
                    cpasync16(sB + (gn % 3) * 16384 + tid * 16 + k * 4096,
                              bsrc + (size_t)gn * 16384 + tid * 16 + k * 4096);
            }
            CP_COMMIT();

            const uint32_t aCk = sA + (uint32_t)c * 16384;
            const uint32_t bCk = sB + (uint32_t)(g % 3) * 16384;
#pragma unroll
            for (int ks = 0; ks < 4; ks++) {
                uint32_t a[4][4], b[2][4];
#pragma unroll
                for (int mi = 0; mi < 4; mi++)
                    ldsm4(aCk + aoff[mi] + acol[ks], a[mi][0], a[mi][1], a[mi][2], a[mi][3]);
#pragma unroll
                for (int nip = 0; nip < 2; nip++)
                    ldsm4(bCk + boff[nip] + bcol[ks], b[nip][0], b[nip][1], b[nip][2], b[nip][3]);
#pragma unroll
                for (int mi = 0; mi < 4; mi++) {
#pragma unroll
                    for (int ni = 0; ni < 4; ni++)
                        mma16816(acc[mi][ni], a[mi], &b[ni >> 1][(ni & 1) * 2]);
                }
            }
        }

        // epilogue: masked exp-sum, registers only
        const int colbase = slice * 8192 + nt * 128 + warp_n * 32 + (lane & 3) * 2;
#pragma unroll
        for (int mi = 0; mi < 4; mi++) {
#pragma unroll
            for (int ni = 0; ni < 4; ni++) {
#pragma unroll
                for (int e = 0; e < 4; e++) {
                    int col = colbase + ni * 8 + (e & 1);
                    int myc = (e >> 1) ? myhi[mi] : mylo[mi];
                    float ex = __expf(acc[mi][ni][e] - 2.0f);
                    if (col != myc) racc[mi * 2 + (e >> 1)] += ex;
                }
            }
        }
    }

    // final reduce across the 4 lanes sharing a row, then global atomics
#pragma unroll
    for (int j = 0; j < 8; j++) {
        float v = racc[j];
        v += __shfl_xor_sync(0xffffffffu, v, 1);
        v += __shfl_xor_sync(0xffffffffu, v, 2);
        if ((lane & 3) == 0) {
            int row = mbase + warp_m * 64 + (j >> 1) * 16 + (j & 1) * 8 + (lane >> 2);
            atomicAdd(&g_ssum[row], v);
        }
    }
}

// ---- EMA closed form ----
__global__ void proto_copy_kernel(const float* __restrict__ proto, float* __restrict__ out) {
    int idx = blockIdx.x * blockDim.x + threadIdx.x;
    if (idx < NK * ND) out[1 + idx] = proto[idx] * g_fac[idx >> 9];
}
__global__ void scatter_kernel(const float* __restrict__ emb, float* __restrict__ out) {
    int b = blockIdx.x;
    int c = g_cid[b];
    float w = 0.1f * pow09(g_counts[c] - 1 - g_ranks[b]);
    float* dst = out + 1 + (size_t)c * ND;
    const float* x = emb + (size_t)b * ND;
    for (int d = threadIdx.x; d < ND; d += blockDim.x)
        atomicAdd(&dst[d], w * x[d]);
}

__global__ void loss_kernel(float* __restrict__ out) {
    __shared__ float red[256];
    int tid = threadIdx.x;
    float acc = 0.f;
    for (int r = tid; r < NB; r += 256)
        acc += (2.0f + logf(g_ssum[r])) - g_pos[r];
    red[tid] = acc;
    __syncthreads();
    for (int o = 128; o; o >>= 1) {
        if (tid < o) red[tid] += red[tid + o];
        __syncthreads();
    }
    if (tid == 0) out[0] = red[0] / (float)NB;
}

extern "C" void kernel_launch(void* const* d_in, const int* in_sizes, int n_in,
                              void* d_out, int out_size) {
    const float* emb   = (const float*)d_in[0];
    const int*   cidr  = (const int*)d_in[1];
    const float* proto = (const float*)d_in[2];
    float* out = (float*)d_out;

    static int attr_done = 0;
    if (!attr_done) {
        cudaFuncSetAttribute(gemm_hmma_kernel, cudaFuncAttributeMaxDynamicSharedMemorySize, SMEMSZ);
        attr_done = 1;
    }

    detect_kernel<<<1, 256>>>(cidr);
    convert_cid_kernel<<<NB / 256, 256>>>(cidr);

    l2norm_img_kernel<<<NB / 8, 256>>>(emb, NB, 2.0f, 0);
    l2norm_img_kernel<<<NK / 8, 256>>>(proto, NK, 1.0f, 1);

    zero_counts_kernel<<<NK / 256, 256>>>();
    count_kernel<<<NB / 256, 256>>>();
    fac_kernel<<<NK / 256, 256>>>();
    rank_kernel<<<NB / 256, 256>>>();

    gemm_hmma_kernel<<<dim3(64, 2), 256, SMEMSZ>>>();

    pos_kernel<<<NB * 32 / 256, 256>>>(emb, proto);
    proto_copy_kernel<<<(NK * ND) / 256, 256>>>(proto, out);
    scatter_kernel<<<NB, 128>>>(emb, out);

    loss_kernel<<<1, 256>>>(out);
}